// round 13
// baseline (speedup 1.0000x reference)
#include <cuda_runtime.h>

// GraphDenoiser N=768, F=256, H=128 — 7 launches, full-K small GEMMs,
// scalar-FMA GEMM inner loops (f32x2 reverted: repack movs cost > FFMA2 gain),
// f32x2 kept only in edge kernel (operand reuse amortizes packing).

#define NN   768
#define FDIM 256
#define HH   128
#define MN   (NN * HH)       // 98304
#define MN2  (NN * 2 * HH)   // 196608

typedef unsigned long long ull;

// ------------------- scratch -------------------
__device__ __align__(16) float g_dinv[NN];
__device__ __align__(16) float g_bpack[HH * 2 * HH];
__device__ __align__(16) float g_c[HH];
__device__ __align__(16) float g_xwf[MN];       // hwf
__device__ __align__(16) float g_pqf[MN2];
__device__ __align__(16) float g_sig[NN * NN];
__device__ __align__(16) float g_S1[12 * MN];   // adj-gemm slabs
__device__ __align__(16) float g_S2[2 * MN];    // xw k-slabs

// ------------------- f32x2 helpers (edge kernel only) -------------------
__device__ __forceinline__ ull pk2(float lo, float hi) {
    ull d;
    asm("mov.b64 %0, {%1, %2};" : "=l"(d) : "f"(lo), "f"(hi));
    return d;
}
__device__ __forceinline__ float2 upk2(ull d) {
    float2 v;
    asm("mov.b64 {%0, %1}, %2;" : "=f"(v.x), "=f"(v.y) : "l"(d));
    return v;
}
#define F32X2_ADD(d, a, b) \
    asm("add.rn.f32x2 %0, %1, %2;" : "=l"(d) : "l"(a), "l"(b))
#define F32X2_FMA(d, a, b, c) \
    asm("fma.rn.f32x2 %0, %1, %2, %3;" : "=l"(d) : "l"(a), "l"(b), "l"(c))

// ------------------- small GEMM: 16 rows x 128 cols, BK=16, double-buffered --
// AMODE: 0 plain | 2 relu(dinv[row] * sum SA slabs)
template<int AMODE, int SA>
__device__ __forceinline__ void gemm16(
    const float* __restrict__ A, const float* __restrict__ B,
    float* __restrict__ out, float* sm,
    int row0, int bcol0, int ocol0, int kb, int nsteps,
    int lda, int ldb, int ldo, bool addc)
{
    float* smA = sm;               // [2][16][17]  As[buf][k][row]
    float* smB = sm + 2 * 16 * 17; // [2][16][132]
    const int tid = threadIdx.x;
    const int ty = tid >> 5;                 // 0..15 output row
    const int tx = tid & 31;                 // cols tx*4
    const int arow = tid >> 4, akk = tid & 15;   // A loader (tid<256)
    const int br = tid >> 5, bc4 = (tid & 31) * 4;

    auto ldA = [&](int k0) -> float {
        int gr = row0 + arow, gk = k0 + akk;
        if (AMODE == 2) {
            float v = 0.f;
            const float* base = A + gr * lda + gk;
            #pragma unroll
            for (int s = 0; s < SA; s++) v += base[s * MN];
            return fmaxf(v * g_dinv[gr], 0.f);
        }
        return A[gr * lda + gk];
    };
    auto ldB = [&](int k0) -> float4 {
        return *(const float4*)&B[(k0 + br) * ldb + bcol0 + bc4];
    };

    float a_reg = 0.f;
    if (tid < 256) a_reg = ldA(kb);
    float4 b_reg = ldB(kb);
    int buf = 0;
    if (tid < 256) smA[akk * 17 + arow] = a_reg;
    *(float4*)&smB[br * 132 + bc4] = b_reg;
    __syncthreads();

    float acc[4] = {};
    for (int s = 0; s < nsteps; s++) {
        bool more = (s + 1 < nsteps);
        float a_n = 0.f; float4 b_n;
        if (more) {
            if (tid < 256) a_n = ldA(kb + (s + 1) * 16);
            b_n = ldB(kb + (s + 1) * 16);
        }
        const float* cA = smA + buf * 16 * 17;
        const float* cB = smB + buf * 16 * 132;
        #pragma unroll
        for (int k = 0; k < 16; k++) {
            float a = cA[k * 17 + ty];
            float4 b4 = *(const float4*)&cB[k * 132 + tx * 4];
            acc[0] = fmaf(a, b4.x, acc[0]);
            acc[1] = fmaf(a, b4.y, acc[1]);
            acc[2] = fmaf(a, b4.z, acc[2]);
            acc[3] = fmaf(a, b4.w, acc[3]);
        }
        if (more) {
            buf ^= 1;
            float* nA = smA + buf * 16 * 17;
            float* nB = smB + buf * 16 * 132;
            if (tid < 256) nA[akk * 17 + arow] = a_n;
            *(float4*)&nB[br * 132 + bc4] = b_n;
            __syncthreads();
        }
    }
    float4 res = make_float4(acc[0], acc[1], acc[2], acc[3]);
    if (addc) {
        float4 c = *(const float4*)&g_c[tx * 4];   // ocol0==HH when addc
        res.x += c.x; res.y += c.y; res.z += c.z; res.w += c.w;
    }
    *(float4*)&out[(row0 + ty) * ldo + ocol0 + tx * 4] = res;
}

// ------------------- K1: prelude + xw (full K, 2 k-slabs) -------------------
__global__ void __launch_bounds__(512)
k_pre(const float* __restrict__ x, const float* __restrict__ w1,
      const float* __restrict__ adj, const float* __restrict__ time_emb,
      const int* __restrict__ t_ptr, const float* __restrict__ we1,
      const float* __restrict__ be1)
{
    __shared__ __align__(16) float sm[4768];
    const int b = blockIdx.x;
    const int tid = threadIdx.x;
    if (b < 96) {
        int rowtile = b % 48, z = b / 48;       // z slab over k halves of 256
        gemm16<0, 1>(x, w1, g_S2 + z * MN, sm,
                     rowtile * 16, 0, 0, z * 128, 8, FDIM, HH, HH, false);
    } else {
        int rb = b - 96;                        // 0..47
        {   // dinv: 16 warps/block x 48 blocks = 768 rows
            int row  = rb * 16 + (tid >> 5);
            int lane = tid & 31;
            const float4* r = (const float4*)(adj + row * NN);
            float s = 0.f;
            #pragma unroll
            for (int j = lane; j < NN / 4; j += 32) {
                float4 v = r[j];
                s += (v.x + v.y) + (v.z + v.w);
            }
            #pragma unroll
            for (int o = 16; o; o >>= 1) s += __shfl_xor_sync(0xffffffffu, s, o);
            s += 1.0f;
            if (lane == 0) g_dinv[row] = (s > 0.f) ? rsqrtf(s) : 0.f;
        }
        for (int idx = rb * 512 + tid; idx < HH * 2 * HH; idx += 48 * 512) {
            int k = idx >> 8, n = idx & 255;
            g_bpack[idx] = (n < HH) ? we1[k * HH + n] : we1[(HH + k) * HH + (n - HH)];
        }
        if (rb == 47 && tid < HH) {
            int t = t_ptr[0];
            const float* te = time_emb + t * HH;
            float s = be1[tid];
            #pragma unroll 8
            for (int k = 0; k < HH; k++)
                s = fmaf(te[k], we1[(2 * HH + k) * HH + tid], s);
            g_c[tid] = s;
        }
    }
}

// ------------------- adj GEMM: (adj+I) @ [dinv_k * sum SB slabs(B)] ----------
// 64x128 tile, split z=12 (kchunk 64, nsteps=4), scalar FMA inner.
template<int SB>
__global__ void __launch_bounds__(512)
k_adj(const float* __restrict__ adj, const float* __restrict__ Bsrc) {
    __shared__ __align__(16) float sm[2 * 16 * 68 + 2 * 16 * 132];
    float* smA = sm;
    float* smB = sm + 2 * 16 * 68;
    const int row0 = (blockIdx.x % 12) * 64;
    const int z    = blockIdx.x / 12;
    const int kb   = z * 64;
    const int tid  = threadIdx.x;
    const int ty = tid >> 5, tx = tid & 31;
    const int ar = tid >> 3, ac2 = (tid & 7) * 2;
    const int br = tid >> 5, bc4 = (tid & 31) * 4;
    const int gr = row0 + ar;

    auto ldA = [&](int k0) -> float2 {
        int gk = k0 + ac2;
        float2 v = *(const float2*)&adj[gr * NN + gk];
        if (gr == gk)          v.x += 1.0f;
        else if (gr == gk + 1) v.y += 1.0f;
        return v;
    };
    auto ldB = [&](int k0) -> float4 {
        int gk = k0 + br;
        float4 v = make_float4(0.f, 0.f, 0.f, 0.f);
        const float* base = Bsrc + gk * HH + bc4;
        #pragma unroll
        for (int s = 0; s < SB; s++) {
            float4 u = *(const float4*)(base + s * MN);
            v.x += u.x; v.y += u.y; v.z += u.z; v.w += u.w;
        }
        float sc = g_dinv[gk];
        v.x *= sc; v.y *= sc; v.z *= sc; v.w *= sc;
        return v;
    };

    float acc[4][4] = {};
    float2 a_reg = ldA(kb);
    float4 b_reg = ldB(kb);
    int buf = 0;
    smA[(ac2 + 0) * 68 + ar] = a_reg.x;
    smA[(ac2 + 1) * 68 + ar] = a_reg.y;
    *(float4*)&smB[br * 132 + bc4] = b_reg;
    __syncthreads();

    for (int s = 0; s < 4; s++) {
        bool more = (s + 1 < 4);
        float2 a_n; float4 b_n;
        if (more) {
            a_n = ldA(kb + (s + 1) * 16);
            b_n = ldB(kb + (s + 1) * 16);
        }
        const float* cA = smA + buf * 16 * 68;
        const float* cB = smB + buf * 16 * 132;
        #pragma unroll
        for (int k = 0; k < 16; k++) {
            float4 a4 = *(const float4*)&cA[k * 68 + ty * 4];
            float4 b4 = *(const float4*)&cB[k * 132 + tx * 4];
            float aa[4] = {a4.x, a4.y, a4.z, a4.w};
            float bb[4] = {b4.x, b4.y, b4.z, b4.w};
            #pragma unroll
            for (int m = 0; m < 4; m++)
                #pragma unroll
                for (int n = 0; n < 4; n++)
                    acc[m][n] = fmaf(aa[m], bb[n], acc[m][n]);
        }
        if (more) {
            buf ^= 1;
            float* nA = smA + buf * 16 * 68;
            float* nB = smB + buf * 16 * 132;
            nA[(ac2 + 0) * 68 + ar] = a_n.x;
            nA[(ac2 + 1) * 68 + ar] = a_n.y;
            *(float4*)&nB[br * 132 + bc4] = b_n;
            __syncthreads();
        }
    }
    float* dst = g_S1 + (size_t)z * MN;
    #pragma unroll
    for (int m = 0; m < 4; m++) {
        *(float4*)&dst[(row0 + ty * 4 + m) * HH + tx * 4] =
            make_float4(acc[m][0], acc[m][1], acc[m][2], acc[m][3]);
    }
}

// ------------------- hw = relu(dinv*sum12 S1) @ w2 -> hwf -------------------
__global__ void __launch_bounds__(512)
k_hw(const float* __restrict__ w2) {
    __shared__ __align__(16) float sm[4768];
    gemm16<2, 12>(g_S1, w2, g_xwf, sm,
                  blockIdx.x * 16, 0, 0, 0, 8, HH, HH, HH, false);
}

// ------------------- pq = relu(dinv*sum12 S1) @ bpack (+c on q half) --------
__global__ void __launch_bounds__(512)
k_pq() {
    __shared__ __align__(16) float sm[4768];
    int rowtile = blockIdx.x % 48, col = blockIdx.x / 48;
    gemm16<2, 12>(g_S1, g_bpack, g_pqf, sm,
                  rowtile * 16, col * 128, col * 128, 0, 8, HH, 2 * HH, 2 * HH,
                  col == 1);
}

// ------------------- edge MLP + sigmoid (f32x2 packed rows) -------------------
__global__ void __launch_bounds__(512)
k_edge(const float* __restrict__ we2, const float* __restrict__ be2) {
    __shared__ __align__(16) float Ps[32 * 68];
    __shared__ __align__(8)  float Qs[32 * 66];
    __shared__ float Ws[HH];
    const int i0 = (blockIdx.x / 12) * 64;
    const int j0 = (blockIdx.x % 12) * 64;
    const int tid = threadIdx.x;
    const int ty = tid >> 5, tx = tid & 31;
    const int lr = tid >> 3, lc4 = (tid & 7) * 4;
    if (tid < HH) Ws[tid] = we2[tid];

    ull acc2[2][2] = {};
    #pragma unroll
    for (int h0 = 0; h0 < HH; h0 += 32) {
        __syncthreads();
        float4 pv = *(const float4*)&g_pqf[(i0 + lr) * 256 + h0 + lc4];
        float4 qv = *(const float4*)&g_pqf[(j0 + lr) * 256 + HH + h0 + lc4];
        Ps[(lc4 + 0) * 68 + lr] = pv.x;
        Ps[(lc4 + 1) * 68 + lr] = pv.y;
        Ps[(lc4 + 2) * 68 + lr] = pv.z;
        Ps[(lc4 + 3) * 68 + lr] = pv.w;
        Qs[(lc4 + 0) * 66 + lr] = qv.x;
        Qs[(lc4 + 1) * 66 + lr] = qv.y;
        Qs[(lc4 + 2) * 66 + lr] = qv.z;
        Qs[(lc4 + 3) * 66 + lr] = qv.w;
        __syncthreads();
        #pragma unroll
        for (int k = 0; k < 32; k++) {
            float w = Ws[h0 + k];
            ull w2 = pk2(w, w);
            float4 p4 = *(const float4*)&Ps[k * 68 + ty * 4];
            float2 q2 = *(const float2*)&Qs[k * 66 + tx * 2];
            ull pp[2] = { pk2(p4.x, p4.y), pk2(p4.z, p4.w) };
            ull qd[2] = { pk2(q2.x, q2.x), pk2(q2.y, q2.y) };
            #pragma unroll
            for (int mp = 0; mp < 2; mp++) {
                #pragma unroll
                for (int n = 0; n < 2; n++) {
                    ull sum;
                    F32X2_ADD(sum, pp[mp], qd[n]);
                    float2 sv = upk2(sum);
                    sv.x = fmaxf(sv.x, 0.f);
                    sv.y = fmaxf(sv.y, 0.f);
                    ull rv = pk2(sv.x, sv.y);
                    F32X2_FMA(acc2[mp][n], rv, w2, acc2[mp][n]);
                }
            }
        }
    }
    float bb = be2[0];
    #pragma unroll
    for (int mp = 0; mp < 2; mp++) {
        float2 c0 = upk2(acc2[mp][0]);
        float2 c1 = upk2(acc2[mp][1]);
        float2 o0, o1;
        o0.x = 1.0f / (1.0f + __expf(-(c0.x + bb)));
        o0.y = 1.0f / (1.0f + __expf(-(c1.x + bb)));
        o1.x = 1.0f / (1.0f + __expf(-(c0.y + bb)));
        o1.y = 1.0f / (1.0f + __expf(-(c1.y + bb)));
        *(float2*)&g_sig[(i0 + ty * 4 + mp * 2 + 0) * NN + j0 + tx * 2] = o0;
        *(float2*)&g_sig[(i0 + ty * 4 + mp * 2 + 1) * NN + j0 + tx * 2] = o1;
    }
}

// ------------------- symmetrize -------------------
__global__ void __launch_bounds__(512)
k_sym(float* __restrict__ out) {
    __shared__ __align__(16) float T[64 * 65];
    const int r0 = (blockIdx.x / 12) * 64;
    const int c0 = (blockIdx.x % 12) * 64;
    const int tid = threadIdx.x;
    int row = tid >> 3, c8 = (tid & 7) * 8;
    float4 v0 = *(const float4*)&g_sig[(c0 + row) * NN + r0 + c8];
    float4 v1 = *(const float4*)&g_sig[(c0 + row) * NN + r0 + c8 + 4];
    T[row * 65 + c8 + 0] = v0.x; T[row * 65 + c8 + 1] = v0.y;
    T[row * 65 + c8 + 2] = v0.z; T[row * 65 + c8 + 3] = v0.w;
    T[row * 65 + c8 + 4] = v1.x; T[row * 65 + c8 + 5] = v1.y;
    T[row * 65 + c8 + 6] = v1.z; T[row * 65 + c8 + 7] = v1.w;
    __syncthreads();
    float4 a0 = *(const float4*)&g_sig[(r0 + row) * NN + c0 + c8];
    float4 a1 = *(const float4*)&g_sig[(r0 + row) * NN + c0 + c8 + 4];
    float o[8] = {a0.x, a0.y, a0.z, a0.w, a1.x, a1.y, a1.z, a1.w};
    #pragma unroll
    for (int i = 0; i < 8; i++)
        o[i] = 0.5f * (o[i] + T[(c8 + i) * 65 + row]);
    *(float4*)&out[(r0 + row) * NN + c0 + c8]     = make_float4(o[0], o[1], o[2], o[3]);
    *(float4*)&out[(r0 + row) * NN + c0 + c8 + 4] = make_float4(o[4], o[5], o[6], o[7]);
}

// ------------------- launch -------------------
extern "C" void kernel_launch(void* const* d_in, const int* in_sizes, int n_in,
                              void* d_out, int out_size) {
    const float* x        = (const float*)d_in[0];
    const float* adj      = (const float*)d_in[1];
    const float* w1       = (const float*)d_in[2];
    const float* w2       = (const float*)d_in[3];
    const float* time_emb = (const float*)d_in[4];
    const float* we1      = (const float*)d_in[5];
    const float* be1      = (const float*)d_in[6];
    const float* we2      = (const float*)d_in[7];
    const float* be2      = (const float*)d_in[8];
    const int*   t_ptr    = (const int*)d_in[9];
    float* out = (float*)d_out;

    float *S2, *xwf;
    cudaGetSymbolAddress((void**)&S2,  g_S2);
    cudaGetSymbolAddress((void**)&xwf, g_xwf);

    k_pre<<<144, 512>>>(x, w1, adj, time_emb, t_ptr, we1, be1);
    k_adj<2><<<144, 512>>>(adj, S2);     // S1 = (adj+I) @ (dinv*(s0+s1))  [12 slabs]
    k_hw<<<48, 512>>>(w2);               // hwf = relu(dinv*sum12 S1) @ w2
    k_adj<1><<<144, 512>>>(adj, xwf);    // S1 = (adj+I) @ (dinv*hwf)      [12 slabs]
    k_pq<<<96, 512>>>();                 // pqf = relu(dinv*sum12 S1) @ bpack (+c)
    k_edge<<<144, 512>>>(we2, be2);      // sig
    k_sym<<<144, 512>>>(out);            // out = (sig+sig^T)/2
}

// round 15
// speedup vs baseline: 1.0006x; 1.0006x over previous
#include <cuda_runtime.h>

// GraphDenoiser N=768, F=256, H=128 — 9 launches.
// k_adj: 256-thr CTAs, 2/SM, 8x4 micro-tile, 24 k-slabs.
// Dedicated slab-reduce; k_hw/k_pq are clean pipelined GEMMs.

#define NN   768
#define FDIM 256
#define HH   128
#define MN   (NN * HH)       // 98304
#define MN2  (NN * 2 * HH)   // 196608

typedef unsigned long long ull;

// ------------------- scratch -------------------
__device__ __align__(16) float g_dinv[NN];
__device__ __align__(16) float g_bpack[HH * 2 * HH];
__device__ __align__(16) float g_c[HH];
__device__ __align__(16) float g_hf[MN];        // reduced h1 / h2
__device__ __align__(16) float g_pqf[MN2];
__device__ __align__(16) float g_sig[NN * NN];
__device__ __align__(16) float g_S1[24 * MN];   // adj-gemm k-slabs
__device__ __align__(16) float g_S2[2 * MN];    // xw / hw k-slabs

// ------------------- f32x2 helpers (edge kernel only) -------------------
__device__ __forceinline__ ull pk2(float lo, float hi) {
    ull d;
    asm("mov.b64 %0, {%1, %2};" : "=l"(d) : "f"(lo), "f"(hi));
    return d;
}
__device__ __forceinline__ float2 upk2(ull d) {
    float2 v;
    asm("mov.b64 {%0, %1}, %2;" : "=f"(v.x), "=f"(v.y) : "l"(d));
    return v;
}
#define F32X2_ADD(d, a, b) \
    asm("add.rn.f32x2 %0, %1, %2;" : "=l"(d) : "l"(a), "l"(b))
#define F32X2_FMA(d, a, b, c) \
    asm("fma.rn.f32x2 %0, %1, %2, %3;" : "=l"(d) : "l"(a), "l"(b), "l"(c))

// ------------------- small GEMM: 16 rows x 128 cols, BK=16, double-buffered --
__device__ __forceinline__ void gemm16(
    const float* __restrict__ A, const float* __restrict__ B,
    float* __restrict__ out, float* sm,
    int row0, int bcol0, int ocol0, int kb, int nsteps,
    int lda, int ldb, int ldo, bool addc)
{
    float* smA = sm;               // [2][16][17]  As[buf][k][row]
    float* smB = sm + 2 * 16 * 17; // [2][16][132]
    const int tid = threadIdx.x;
    const int ty = tid >> 5;                 // 0..15 output row
    const int tx = tid & 31;                 // cols tx*4
    const int arow = tid >> 4, akk = tid & 15;   // A loader (tid<256)
    const int br = tid >> 5, bc4 = (tid & 31) * 4;

    auto ldA = [&](int k0) -> float {
        return A[(row0 + arow) * lda + k0 + akk];
    };
    auto ldB = [&](int k0) -> float4 {
        return *(const float4*)&B[(k0 + br) * ldb + bcol0 + bc4];
    };

    float a_reg = 0.f;
    if (tid < 256) a_reg = ldA(kb);
    float4 b_reg = ldB(kb);
    int buf = 0;
    if (tid < 256) smA[akk * 17 + arow] = a_reg;
    *(float4*)&smB[br * 132 + bc4] = b_reg;
    __syncthreads();

    float acc[4] = {};
    for (int s = 0; s < nsteps; s++) {
        bool more = (s + 1 < nsteps);
        float a_n = 0.f; float4 b_n;
        if (more) {
            if (tid < 256) a_n = ldA(kb + (s + 1) * 16);
            b_n = ldB(kb + (s + 1) * 16);
        }
        const float* cA = smA + buf * 16 * 17;
        const float* cB = smB + buf * 16 * 132;
        #pragma unroll
        for (int k = 0; k < 16; k++) {
            float a = cA[k * 17 + ty];
            float4 b4 = *(const float4*)&cB[k * 132 + tx * 4];
            acc[0] = fmaf(a, b4.x, acc[0]);
            acc[1] = fmaf(a, b4.y, acc[1]);
            acc[2] = fmaf(a, b4.z, acc[2]);
            acc[3] = fmaf(a, b4.w, acc[3]);
        }
        if (more) {
            buf ^= 1;
            float* nA = smA + buf * 16 * 17;
            float* nB = smB + buf * 16 * 132;
            if (tid < 256) nA[akk * 17 + arow] = a_n;
            *(float4*)&nB[br * 132 + bc4] = b_n;
            __syncthreads();
        }
    }
    float4 res = make_float4(acc[0], acc[1], acc[2], acc[3]);
    if (addc) {
        float4 c = *(const float4*)&g_c[tx * 4];
        res.x += c.x; res.y += c.y; res.z += c.z; res.w += c.w;
    }
    *(float4*)&out[(row0 + ty) * ldo + ocol0 + tx * 4] = res;
}

// ------------------- K1: prelude + xw (full K, 2 k-slabs) -------------------
__global__ void __launch_bounds__(512)
k_pre(const float* __restrict__ x, const float* __restrict__ w1,
      const float* __restrict__ adj, const float* __restrict__ time_emb,
      const int* __restrict__ t_ptr, const float* __restrict__ we1,
      const float* __restrict__ be1)
{
    __shared__ __align__(16) float sm[4768];
    const int b = blockIdx.x;
    const int tid = threadIdx.x;
    if (b < 96) {
        int rowtile = b % 48, z = b / 48;       // z over k halves of 256
        gemm16(x, w1, g_S2 + z * MN, sm,
               rowtile * 16, 0, 0, z * 128, 8, FDIM, HH, HH, false);
    } else {
        int rb = b - 96;                        // 0..47
        {   // dinv: 16 warps/block x 48 blocks = 768 rows
            int row  = rb * 16 + (tid >> 5);
            int lane = tid & 31;
            const float4* r = (const float4*)(adj + row * NN);
            float s = 0.f;
            #pragma unroll
            for (int j = lane; j < NN / 4; j += 32) {
                float4 v = r[j];
                s += (v.x + v.y) + (v.z + v.w);
            }
            #pragma unroll
            for (int o = 16; o; o >>= 1) s += __shfl_xor_sync(0xffffffffu, s, o);
            s += 1.0f;
            if (lane == 0) g_dinv[row] = (s > 0.f) ? rsqrtf(s) : 0.f;
        }
        for (int idx = rb * 512 + tid; idx < HH * 2 * HH; idx += 48 * 512) {
            int k = idx >> 8, n = idx & 255;
            g_bpack[idx] = (n < HH) ? we1[k * HH + n] : we1[(HH + k) * HH + (n - HH)];
        }
        if (rb == 47 && tid < HH) {
            int t = t_ptr[0];
            const float* te = time_emb + t * HH;
            float s = be1[tid];
            #pragma unroll 8
            for (int k = 0; k < HH; k++)
                s = fmaf(te[k], we1[(2 * HH + k) * HH + tid], s);
            g_c[tid] = s;
        }
    }
}

// ------------------- adj GEMM: (adj+I) @ [dinv_k * (slab0+slab1)] ------------
// 256 threads, 2 CTAs/SM. 64 rows x 128 cols, 8x4 micro, kchunk 32 (24 slabs).
__global__ void __launch_bounds__(256, 2)
k_adj(const float* __restrict__ adj, const float* __restrict__ Bsrc) {
    __shared__ __align__(16) float smA[2 * 16 * 68];
    __shared__ __align__(16) float smB[2 * 16 * 132];
    const int row0 = (blockIdx.x % 12) * 64;
    const int z    = blockIdx.x / 12;        // 0..23
    const int kb   = z * 32;
    const int tid  = threadIdx.x;
    const int ty = tid >> 5;                 // 0..7: rows ty*8..+7
    const int tx = tid & 31;                 // cols tx*4
    const int ar = tid >> 2, ac4 = (tid & 3) * 4;   // A: 64 rows x 16 k
    const int br = tid >> 5, bc4 = (tid & 31) * 4;  // B: rows br, br+8

    auto ldA = [&](int k0) -> float4 {
        int gk = k0 + ac4;
        float4 av = *(const float4*)&adj[(row0 + ar) * NN + gk];
        int d = (row0 + ar) - gk;
        if (d >= 0 && d < 4) ((float*)&av)[d] += 1.0f;
        return av;
    };
    auto ldB = [&](int k0, float4& b0, float4& b1) {
        int gk0 = k0 + br, gk1 = gk0 + 8;
        const float* p0 = Bsrc + gk0 * HH + bc4;
        const float* p1 = Bsrc + gk1 * HH + bc4;
        float4 u0 = *(const float4*)p0;
        float4 v0 = *(const float4*)(p0 + MN);
        float4 u1 = *(const float4*)p1;
        float4 v1 = *(const float4*)(p1 + MN);
        float s0 = g_dinv[gk0], s1 = g_dinv[gk1];
        b0 = make_float4((u0.x + v0.x) * s0, (u0.y + v0.y) * s0,
                         (u0.z + v0.z) * s0, (u0.w + v0.w) * s0);
        b1 = make_float4((u1.x + v1.x) * s1, (u1.y + v1.y) * s1,
                         (u1.z + v1.z) * s1, (u1.w + v1.w) * s1);
    };

    float acc[8][4] = {};
    float4 aR = ldA(kb);
    float4 b0R, b1R;
    ldB(kb, b0R, b1R);
    int buf = 0;
    #pragma unroll
    for (int j = 0; j < 4; j++)
        smA[(ac4 + j) * 68 + ar] = ((float*)&aR)[j];
    *(float4*)&smB[br * 132 + bc4]       = b0R;
    *(float4*)&smB[(br + 8) * 132 + bc4] = b1R;
    __syncthreads();

    #pragma unroll
    for (int s = 0; s < 2; s++) {
        bool more = (s == 0);
        float4 aN, b0N, b1N;
        if (more) {
            aN = ldA(kb + 16);
            ldB(kb + 16, b0N, b1N);
        }
        const float* cA = smA + buf * 16 * 68;
        const float* cB = smB + buf * 16 * 132;
        #pragma unroll
        for (int k = 0; k < 16; k++) {
            float4 a0 = *(const float4*)&cA[k * 68 + ty * 8];
            float4 a1 = *(const float4*)&cA[k * 68 + ty * 8 + 4];
            float4 b4 = *(const float4*)&cB[k * 132 + tx * 4];
            float aa[8] = {a0.x, a0.y, a0.z, a0.w, a1.x, a1.y, a1.z, a1.w};
            float bb[4] = {b4.x, b4.y, b4.z, b4.w};
            #pragma unroll
            for (int m = 0; m < 8; m++)
                #pragma unroll
                for (int n = 0; n < 4; n++)
                    acc[m][n] = fmaf(aa[m], bb[n], acc[m][n]);
        }
        if (more) {
            buf ^= 1;
            float* nA = smA + buf * 16 * 68;
            float* nB = smB + buf * 16 * 132;
            #pragma unroll
            for (int j = 0; j < 4; j++)
                nA[(ac4 + j) * 68 + ar] = ((float*)&aN)[j];
            *(float4*)&nB[br * 132 + bc4]       = b0N;
            *(float4*)&nB[(br + 8) * 132 + bc4] = b1N;
            __syncthreads();
        }
    }
    float* dst = g_S1 + (size_t)z * MN;
    #pragma unroll
    for (int m = 0; m < 8; m++) {
        *(float4*)&dst[(row0 + ty * 8 + m) * HH + tx * 4] =
            make_float4(acc[m][0], acc[m][1], acc[m][2], acc[m][3]);
    }
}

// ------------------- reduce 24 slabs: hf = relu(dinv[row] * sum24) ----------
__global__ void __launch_bounds__(256)
k_red(float* __restrict__ dst) {
    int idx4 = (blockIdx.x * 256 + threadIdx.x) * 4;   // 96*256*4 = MN
    float4 v = *(const float4*)&g_S1[idx4];
    #pragma unroll
    for (int s = 1; s < 24; s++) {
        float4 u = *(const float4*)&g_S1[(size_t)s * MN + idx4];
        v.x += u.x; v.y += u.y; v.z += u.z; v.w += u.w;
    }
    float sc = g_dinv[idx4 >> 7];
    v.x = fmaxf(v.x * sc, 0.f); v.y = fmaxf(v.y * sc, 0.f);
    v.z = fmaxf(v.z * sc, 0.f); v.w = fmaxf(v.w * sc, 0.f);
    *(float4*)&dst[idx4] = v;
}

// ------------------- hw = hf @ w2 -> S2 (2 k-slabs) -------------------
__global__ void __launch_bounds__(512)
k_hw(const float* __restrict__ w2) {
    __shared__ __align__(16) float sm[4768];
    int rowtile = blockIdx.x % 48, z = blockIdx.x / 48;   // z 0..1, kchunk 64
    gemm16(g_hf, w2, g_S2 + z * MN, sm,
           rowtile * 16, 0, 0, z * 64, 4, HH, HH, HH, false);
}

// ------------------- pq = hf @ bpack (+c on q half) -------------------
__global__ void __launch_bounds__(512)
k_pq() {
    __shared__ __align__(16) float sm[4768];
    int rowtile = blockIdx.x % 48, col = blockIdx.x / 48;
    gemm16(g_hf, g_bpack, g_pqf, sm,
           rowtile * 16, col * 128, col * 128, 0, 8, HH, 2 * HH, 2 * HH,
           col == 1);
}

// ------------------- edge MLP + sigmoid (f32x2 packed rows) -------------------
__global__ void __launch_bounds__(512)
k_edge(const float* __restrict__ we2, const float* __restrict__ be2) {
    __shared__ __align__(16) float Ps[32 * 68];
    __shared__ __align__(8)  float Qs[32 * 66];
    __shared__ float Ws[HH];
    const int i0 = (blockIdx.x / 12) * 64;
    const int j0 = (blockIdx.x % 12) * 64;
    const int tid = threadIdx.x;
    const int ty = tid >> 5, tx = tid & 31;
    const int lr = tid >> 3, lc4 = (tid & 7) * 4;
    if (tid < HH) Ws[tid] = we2[tid];

    ull acc2[2][2] = {};
    #pragma unroll
    for (int h0 = 0; h0 < HH; h0 += 32) {
        __syncthreads();
        float4 pv = *(const float4*)&g_pqf[(i0 + lr) * 256 + h0 + lc4];
        float4 qv = *(const float4*)&g_pqf[(j0 + lr) * 256 + HH + h0 + lc4];
        Ps[(lc4 + 0) * 68 + lr] = pv.x;
        Ps[(lc4 + 1) * 68 + lr] = pv.y;
        Ps[(lc4 + 2) * 68 + lr] = pv.z;
        Ps[(lc4 + 3) * 68 + lr] = pv.w;
        Qs[(lc4 + 0) * 66 + lr] = qv.x;
        Qs[(lc4 + 1) * 66 + lr] = qv.y;
        Qs[(lc4 + 2) * 66 + lr] = qv.z;
        Qs[(lc4 + 3) * 66 + lr] = qv.w;
        __syncthreads();
        #pragma unroll
        for (int k = 0; k < 32; k++) {
            float w = Ws[h0 + k];
            ull w2 = pk2(w, w);
            float4 p4 = *(const float4*)&Ps[k * 68 + ty * 4];
            float2 q2 = *(const float2*)&Qs[k * 66 + tx * 2];
            ull pp[2] = { pk2(p4.x, p4.y), pk2(p4.z, p4.w) };
            ull qd[2] = { pk2(q2.x, q2.x), pk2(q2.y, q2.y) };
            #pragma unroll
            for (int mp = 0; mp < 2; mp++) {
                #pragma unroll
                for (int n = 0; n < 2; n++) {
                    ull sum;
                    F32X2_ADD(sum, pp[mp], qd[n]);
                    float2 sv = upk2(sum);
                    sv.x = fmaxf(sv.x, 0.f);
                    sv.y = fmaxf(sv.y, 0.f);
                    ull rv = pk2(sv.x, sv.y);
                    F32X2_FMA(acc2[mp][n], rv, w2, acc2[mp][n]);
                }
            }
        }
    }
    float bb = be2[0];
    #pragma unroll
    for (int mp = 0; mp < 2; mp++) {
        float2 c0 = upk2(acc2[mp][0]);
        float2 c1 = upk2(acc2[mp][1]);
        float2 o0, o1;
        o0.x = 1.0f / (1.0f + __expf(-(c0.x + bb)));
        o0.y = 1.0f / (1.0f + __expf(-(c1.x + bb)));
        o1.x = 1.0f / (1.0f + __expf(-(c0.y + bb)));
        o1.y = 1.0f / (1.0f + __expf(-(c1.y + bb)));
        *(float2*)&g_sig[(i0 + ty * 4 + mp * 2 + 0) * NN + j0 + tx * 2] = o0;
        *(float2*)&g_sig[(i0 + ty * 4 + mp * 2 + 1) * NN + j0 + tx * 2] = o1;
    }
}

// ------------------- symmetrize -------------------
__global__ void __launch_bounds__(512)
k_sym(float* __restrict__ out) {
    __shared__ __align__(16) float T[64 * 65];
    const int r0 = (blockIdx.x / 12) * 64;
    const int c0 = (blockIdx.x % 12) * 64;
    const int tid = threadIdx.x;
    int row = tid >> 3, c8 = (tid & 7) * 8;
    float4 v0 = *(const float4*)&g_sig[(c0 + row) * NN + r0 + c8];
    float4 v1 = *(const float4*)&g_sig[(c0 + row) * NN + r0 + c8 + 4];
    T[row * 65 + c8 + 0] = v0.x; T[row * 65 + c8 + 1] = v0.y;
    T[row * 65 + c8 + 2] = v0.z; T[row * 65 + c8 + 3] = v0.w;
    T[row * 65 + c8 + 4] = v1.x; T[row * 65 + c8 + 5] = v1.y;
    T[row * 65 + c8 + 6] = v1.z; T[row * 65 + c8 + 7] = v1.w;
    __syncthreads();
    float4 a0 = *(const float4*)&g_sig[(r0 + row) * NN + c0 + c8];
    float4 a1 = *(const float4*)&g_sig[(r0 + row) * NN + c0 + c8 + 4];
    float o[8] = {a0.x, a0.y, a0.z, a0.w, a1.x, a1.y, a1.z, a1.w};
    #pragma unroll
    for (int i = 0; i < 8; i++)
        o[i] = 0.5f * (o[i] + T[(c8 + i) * 65 + row]);
    *(float4*)&out[(r0 + row) * NN + c0 + c8]     = make_float4(o[0], o[1], o[2], o[3]);
    *(float4*)&out[(r0 + row) * NN + c0 + c8 + 4] = make_float4(o[4], o[5], o[6], o[7]);
}

// ------------------- launch -------------------
extern "C" void kernel_launch(void* const* d_in, const int* in_sizes, int n_in,
                              void* d_out, int out_size) {
    const float* x        = (const float*)d_in[0];
    const float* adj      = (const float*)d_in[1];
    const float* w1       = (const float*)d_in[2];
    const float* w2       = (const float*)d_in[3];
    const float* time_emb = (const float*)d_in[4];
    const float* we1      = (const float*)d_in[5];
    const float* be1      = (const float*)d_in[6];
    const float* we2      = (const float*)d_in[7];
    const float* be2      = (const float*)d_in[8];
    const int*   t_ptr    = (const int*)d_in[9];
    float* out = (float*)d_out;

    float *S2, *hf;
    cudaGetSymbolAddress((void**)&S2, g_S2);
    cudaGetSymbolAddress((void**)&hf, g_hf);

    k_pre<<<144, 512>>>(x, w1, adj, time_emb, t_ptr, we1, be1);
    k_adj<<<288, 256>>>(adj, S2);      // S1 = (adj+I) @ (dinv*(xw0+xw1))  [24 slabs]
    k_red<<<96, 256>>>(hf);            // h1f = relu(dinv * sum24 S1)
    k_hw<<<96, 512>>>(w2);             // S2 = h1f @ w2                    [2 slabs]
    k_adj<<<288, 256>>>(adj, S2);      // S1 = (adj+I) @ (dinv*(hw0+hw1))  [24 slabs]
    k_red<<<96, 256>>>(hf);            // h2f = relu(dinv * sum24 S1)
    k_pq<<<96, 512>>>();               // pqf = h2f @ bpack (+c)
    k_edge<<<144, 512>>>(we2, be2);    // sig
    k_sym<<<144, 512>>>(out);          // out = (sig+sig^T)/2
}

// round 17
// speedup vs baseline: 1.0039x; 1.0033x over previous
#include <cuda_runtime.h>
#include <cuda_bf16.h>
#include <cstdint>

// GraphDenoiser N=768, F=256, H=128 — 9 launches.
// k_adj: bf16 split-precision tensor-core MMA (m16n8k16), 24 k-slabs.
// All other kernels identical to the last passing version.

#define NN   768
#define FDIM 256
#define HH   128
#define MN   (NN * HH)       // 98304
#define MN2  (NN * 2 * HH)   // 196608

typedef unsigned long long ull;

// ------------------- scratch -------------------
__device__ __align__(16) float g_dinv[NN];
__device__ __align__(16) float g_bpack[HH * 2 * HH];
__device__ __align__(16) float g_c[HH];
__device__ __align__(16) float g_hf[MN];        // reduced h1 / h2
__device__ __align__(16) float g_pqf[MN2];
__device__ __align__(16) float g_sig[NN * NN];
__device__ __align__(16) float g_S1[24 * MN];   // adj-gemm k-slabs
__device__ __align__(16) float g_S2[2 * MN];    // xw / hw k-slabs

// ------------------- f32x2 helpers (edge kernel only) -------------------
__device__ __forceinline__ ull pk2(float lo, float hi) {
    ull d;
    asm("mov.b64 %0, {%1, %2};" : "=l"(d) : "f"(lo), "f"(hi));
    return d;
}
__device__ __forceinline__ float2 upk2(ull d) {
    float2 v;
    asm("mov.b64 {%0, %1}, %2;" : "=f"(v.x), "=f"(v.y) : "l"(d));
    return v;
}
#define F32X2_ADD(d, a, b) \
    asm("add.rn.f32x2 %0, %1, %2;" : "=l"(d) : "l"(a), "l"(b))
#define F32X2_FMA(d, a, b, c) \
    asm("fma.rn.f32x2 %0, %1, %2, %3;" : "=l"(d) : "l"(a), "l"(b), "l"(c))

// ------------------- bf16 mma m16n8k16 -------------------
#define MMA16816(cc, aa, b0_, b1_) \
    asm volatile("mma.sync.aligned.m16n8k16.row.col.f32.bf16.bf16.f32 " \
        "{%0,%1,%2,%3}, {%4,%5,%6,%7}, {%8,%9}, {%0,%1,%2,%3};" \
        : "+f"((cc)[0]), "+f"((cc)[1]), "+f"((cc)[2]), "+f"((cc)[3]) \
        : "r"((aa)[0]), "r"((aa)[1]), "r"((aa)[2]), "r"((aa)[3]), \
          "r"(b0_), "r"(b1_))

// ------------------- small GEMM: 16 rows x 128 cols, BK=16, double-buffered --
__device__ __forceinline__ void gemm16(
    const float* __restrict__ A, const float* __restrict__ B,
    float* __restrict__ out, float* sm,
    int row0, int bcol0, int ocol0, int kb, int nsteps,
    int lda, int ldb, int ldo, bool addc)
{
    float* smA = sm;               // [2][16][17]
    float* smB = sm + 2 * 16 * 17; // [2][16][132]
    const int tid = threadIdx.x;
    const int ty = tid >> 5;
    const int tx = tid & 31;
    const int arow = tid >> 4, akk = tid & 15;
    const int br = tid >> 5, bc4 = (tid & 31) * 4;

    auto ldA = [&](int k0) -> float {
        return A[(row0 + arow) * lda + k0 + akk];
    };
    auto ldB = [&](int k0) -> float4 {
        return *(const float4*)&B[(k0 + br) * ldb + bcol0 + bc4];
    };

    float a_reg = 0.f;
    if (tid < 256) a_reg = ldA(kb);
    float4 b_reg = ldB(kb);
    int buf = 0;
    if (tid < 256) smA[akk * 17 + arow] = a_reg;
    *(float4*)&smB[br * 132 + bc4] = b_reg;
    __syncthreads();

    float acc[4] = {};
    for (int s = 0; s < nsteps; s++) {
        bool more = (s + 1 < nsteps);
        float a_n = 0.f; float4 b_n;
        if (more) {
            if (tid < 256) a_n = ldA(kb + (s + 1) * 16);
            b_n = ldB(kb + (s + 1) * 16);
        }
        const float* cA = smA + buf * 16 * 17;
        const float* cB = smB + buf * 16 * 132;
        #pragma unroll
        for (int k = 0; k < 16; k++) {
            float a = cA[k * 17 + ty];
            float4 b4 = *(const float4*)&cB[k * 132 + tx * 4];
            acc[0] = fmaf(a, b4.x, acc[0]);
            acc[1] = fmaf(a, b4.y, acc[1]);
            acc[2] = fmaf(a, b4.z, acc[2]);
            acc[3] = fmaf(a, b4.w, acc[3]);
        }
        if (more) {
            buf ^= 1;
            float* nA = smA + buf * 16 * 17;
            float* nB = smB + buf * 16 * 132;
            if (tid < 256) nA[akk * 17 + arow] = a_n;
            *(float4*)&nB[br * 132 + bc4] = b_n;
            __syncthreads();
        }
    }
    float4 res = make_float4(acc[0], acc[1], acc[2], acc[3]);
    if (addc) {
        float4 c = *(const float4*)&g_c[tx * 4];
        res.x += c.x; res.y += c.y; res.z += c.z; res.w += c.w;
    }
    *(float4*)&out[(row0 + ty) * ldo + ocol0 + tx * 4] = res;
}

// ------------------- K1: prelude + xw (full K, 2 k-slabs) -------------------
__global__ void __launch_bounds__(512)
k_pre(const float* __restrict__ x, const float* __restrict__ w1,
      const float* __restrict__ adj, const float* __restrict__ time_emb,
      const int* __restrict__ t_ptr, const float* __restrict__ we1,
      const float* __restrict__ be1)
{
    __shared__ __align__(16) float sm[4768];
    const int b = blockIdx.x;
    const int tid = threadIdx.x;
    if (b < 96) {
        int rowtile = b % 48, z = b / 48;
        gemm16(x, w1, g_S2 + z * MN, sm,
               rowtile * 16, 0, 0, z * 128, 8, FDIM, HH, HH, false);
    } else {
        int rb = b - 96;
        {
            int row  = rb * 16 + (tid >> 5);
            int lane = tid & 31;
            const float4* r = (const float4*)(adj + row * NN);
            float s = 0.f;
            #pragma unroll
            for (int j = lane; j < NN / 4; j += 32) {
                float4 v = r[j];
                s += (v.x + v.y) + (v.z + v.w);
            }
            #pragma unroll
            for (int o = 16; o; o >>= 1) s += __shfl_xor_sync(0xffffffffu, s, o);
            s += 1.0f;
            if (lane == 0) g_dinv[row] = (s > 0.f) ? rsqrtf(s) : 0.f;
        }
        for (int idx = rb * 512 + tid; idx < HH * 2 * HH; idx += 48 * 512) {
            int k = idx >> 8, n = idx & 255;
            g_bpack[idx] = (n < HH) ? we1[k * HH + n] : we1[(HH + k) * HH + (n - HH)];
        }
        if (rb == 47 && tid < HH) {
            int t = t_ptr[0];
            const float* te = time_emb + t * HH;
            float s = be1[tid];
            #pragma unroll 8
            for (int k = 0; k < HH; k++)
                s = fmaf(te[k], we1[(2 * HH + k) * HH + tid], s);
            g_c[tid] = s;
        }
    }
}

// ------------------- adj GEMM via bf16-split tensor cores -------------------
// C_slab[z] = (adj+I)[:, kb:kb+32] @ (dinv*(slab0+slab1))[kb:kb+32, :]
// 64x128 tile, 256 threads (8 warps: 4 m x 2 n), grid 288 = 12 rowtiles x 24 z.
__global__ void __launch_bounds__(256, 2)
k_adj(const float* __restrict__ adj, const float* __restrict__ Bsrc) {
    __shared__ __align__(16) __nv_bfloat16 AhS[64 * 36];
    __shared__ __align__(16) __nv_bfloat16 AlS[64 * 36];
    __shared__ __align__(16) __nv_bfloat16 BhS[128 * 36];
    __shared__ __align__(16) __nv_bfloat16 BlS[128 * 36];
    const int row0 = (blockIdx.x % 12) * 64;
    const int z    = blockIdx.x / 12;        // 0..23
    const int kb   = z * 32;
    const int tid  = threadIdx.x;

    // ---- A convert+split: 64 rows x 32 k (8 floats/thread) ----
    {
        int row = tid >> 2, kk8 = (tid & 3) * 8;
        const float* src = adj + (row0 + row) * NN + kb + kk8;
        float v[8];
        *(float4*)&v[0] = *(const float4*)src;
        *(float4*)&v[4] = *(const float4*)(src + 4);
        int d = (row0 + row) - (kb + kk8);
        if (d >= 0 && d < 8) v[d] += 1.0f;    // + identity (pre-split)
        #pragma unroll
        for (int j = 0; j < 8; j += 2) {
            __nv_bfloat16 h0 = __float2bfloat16(v[j]);
            __nv_bfloat16 h1 = __float2bfloat16(v[j + 1]);
            __nv_bfloat162 hp; hp.x = h0; hp.y = h1;
            __nv_bfloat162 lp;
            lp.x = __float2bfloat16(v[j]     - __bfloat162float(h0));
            lp.y = __float2bfloat16(v[j + 1] - __bfloat162float(h1));
            *(__nv_bfloat162*)&AhS[row * 36 + kk8 + j] = hp;
            *(__nv_bfloat162*)&AlS[row * 36 + kk8 + j] = lp;
        }
    }
    // ---- B convert+split (stored transposed [n][k]): 32 k x 128 n ----
    {
        int kp = (tid & 15) * 2, n8 = (tid >> 4) * 8;
        float v[2][8];
        #pragma unroll
        for (int kk = 0; kk < 2; kk++) {
            int gk = kb + kp + kk;
            const float* p = Bsrc + gk * HH + n8;
            float4 u0 = *(const float4*)p;
            float4 u1 = *(const float4*)(p + 4);
            float4 w0 = *(const float4*)(p + MN);
            float4 w1 = *(const float4*)(p + MN + 4);
            float sc = g_dinv[gk];
            v[kk][0] = (u0.x + w0.x) * sc; v[kk][1] = (u0.y + w0.y) * sc;
            v[kk][2] = (u0.z + w0.z) * sc; v[kk][3] = (u0.w + w0.w) * sc;
            v[kk][4] = (u1.x + w1.x) * sc; v[kk][5] = (u1.y + w1.y) * sc;
            v[kk][6] = (u1.z + w1.z) * sc; v[kk][7] = (u1.w + w1.w) * sc;
        }
        #pragma unroll
        for (int j = 0; j < 8; j++) {
            float a = v[0][j], b = v[1][j];
            __nv_bfloat16 h0 = __float2bfloat16(a);
            __nv_bfloat16 h1 = __float2bfloat16(b);
            __nv_bfloat162 hp; hp.x = h0; hp.y = h1;
            __nv_bfloat162 lp;
            lp.x = __float2bfloat16(a - __bfloat162float(h0));
            lp.y = __float2bfloat16(b - __bfloat162float(h1));
            *(__nv_bfloat162*)&BhS[(n8 + j) * 36 + kp] = hp;
            *(__nv_bfloat162*)&BlS[(n8 + j) * 36 + kp] = lp;
        }
    }
    __syncthreads();

    // ---- mma: each warp computes 16 rows x 64 cols ----
    const int wid = tid >> 5, lane = tid & 31;
    const int wm = wid & 3, wn = wid >> 2;       // wm: m-tile 0..3, wn: n-half
    const int g = lane >> 2, tg = lane & 3;
    float c[8][4] = {};
    #pragma unroll
    for (int ks = 0; ks < 2; ks++) {
        const int k0 = ks * 16;
        const int rb0 = wm * 16 + g;
        uint32_t ah[4], al[4];
        ah[0] = *(const uint32_t*)&AhS[(rb0    ) * 36 + k0 + tg * 2];
        ah[1] = *(const uint32_t*)&AhS[(rb0 + 8) * 36 + k0 + tg * 2];
        ah[2] = *(const uint32_t*)&AhS[(rb0    ) * 36 + k0 + tg * 2 + 8];
        ah[3] = *(const uint32_t*)&AhS[(rb0 + 8) * 36 + k0 + tg * 2 + 8];
        al[0] = *(const uint32_t*)&AlS[(rb0    ) * 36 + k0 + tg * 2];
        al[1] = *(const uint32_t*)&AlS[(rb0 + 8) * 36 + k0 + tg * 2];
        al[2] = *(const uint32_t*)&AlS[(rb0    ) * 36 + k0 + tg * 2 + 8];
        al[3] = *(const uint32_t*)&AlS[(rb0 + 8) * 36 + k0 + tg * 2 + 8];
        #pragma unroll
        for (int na = 0; na < 8; na++) {
            int n = wn * 64 + na * 8 + g;
            uint32_t bh0 = *(const uint32_t*)&BhS[n * 36 + k0 + tg * 2];
            uint32_t bh1 = *(const uint32_t*)&BhS[n * 36 + k0 + tg * 2 + 8];
            uint32_t bl0 = *(const uint32_t*)&BlS[n * 36 + k0 + tg * 2];
            uint32_t bl1 = *(const uint32_t*)&BlS[n * 36 + k0 + tg * 2 + 8];
            MMA16816(c[na], ah, bh0, bh1);
            MMA16816(c[na], al, bh0, bh1);
            MMA16816(c[na], ah, bl0, bl1);
        }
    }
    // ---- store C tile to slab z ----
    float* dst = g_S1 + (size_t)z * MN;
    const int r = row0 + wm * 16 + g;
    #pragma unroll
    for (int na = 0; na < 8; na++) {
        int n = wn * 64 + na * 8 + tg * 2;
        *(float2*)&dst[r * HH + n]       = make_float2(c[na][0], c[na][1]);
        *(float2*)&dst[(r + 8) * HH + n] = make_float2(c[na][2], c[na][3]);
    }
}

// ------------------- reduce 24 slabs: hf = relu(dinv[row] * sum24) ----------
__global__ void __launch_bounds__(256)
k_red(float* __restrict__ dst) {
    int idx4 = (blockIdx.x * 256 + threadIdx.x) * 4;
    float4 v = *(const float4*)&g_S1[idx4];
    #pragma unroll
    for (int s = 1; s < 24; s++) {
        float4 u = *(const float4*)&g_S1[(size_t)s * MN + idx4];
        v.x += u.x; v.y += u.y; v.z += u.z; v.w += u.w;
    }
    float sc = g_dinv[idx4 >> 7];
    v.x = fmaxf(v.x * sc, 0.f); v.y = fmaxf(v.y * sc, 0.f);
    v.z = fmaxf(v.z * sc, 0.f); v.w = fmaxf(v.w * sc, 0.f);
    *(float4*)&dst[idx4] = v;
}

// ------------------- hw = hf @ w2 -> S2 (2 k-slabs) -------------------
__global__ void __launch_bounds__(512)
k_hw(const float* __restrict__ w2) {
    __shared__ __align__(16) float sm[4768];
    int rowtile = blockIdx.x % 48, z = blockIdx.x / 48;
    gemm16(g_hf, w2, g_S2 + z * MN, sm,
           rowtile * 16, 0, 0, z * 64, 4, HH, HH, HH, false);
}

// ------------------- pq = hf @ bpack (+c on q half) -------------------
__global__ void __launch_bounds__(512)
k_pq() {
    __shared__ __align__(16) float sm[4768];
    int rowtile = blockIdx.x % 48, col = blockIdx.x / 48;
    gemm16(g_hf, g_bpack, g_pqf, sm,
           rowtile * 16, col * 128, col * 128, 0, 8, HH, 2 * HH, 2 * HH,
           col == 1);
}

// ------------------- edge MLP + sigmoid (f32x2 packed rows) -------------------
__global__ void __launch_bounds__(512)
k_edge(const float* __restrict__ we2, const float* __restrict__ be2) {
    __shared__ __align__(16) float Ps[32 * 68];
    __shared__ __align__(8)  float Qs[32 * 66];
    __shared__ float Ws[HH];
    const int i0 = (blockIdx.x / 12) * 64;
    const int j0 = (blockIdx.x % 12) * 64;
    const int tid = threadIdx.x;
    const int ty = tid >> 5, tx = tid & 31;
    const int lr = tid >> 3, lc4 = (tid & 7) * 4;
    if (tid < HH) Ws[tid] = we2[tid];

    ull acc2[2][2] = {};
    #pragma unroll
    for (int h0 = 0; h0 < HH; h0 += 32) {
        __syncthreads();
        float4 pv = *(const float4*)&g_pqf[(i0 + lr) * 256 + h0 + lc4];
        float4 qv = *(const float4*)&g_pqf[(j0 + lr) * 256 + HH + h0 + lc4];
        Ps[(lc4 + 0) * 68 + lr] = pv.x;
        Ps[(lc4 + 1) * 68 + lr] = pv.y;
        Ps[(lc4 + 2) * 68 + lr] = pv.z;
        Ps[(lc4 + 3) * 68 + lr] = pv.w;
        Qs[(lc4 + 0) * 66 + lr] = qv.x;
        Qs[(lc4 + 1) * 66 + lr] = qv.y;
        Qs[(lc4 + 2) * 66 + lr] = qv.z;
        Qs[(lc4 + 3) * 66 + lr] = qv.w;
        __syncthreads();
        #pragma unroll
        for (int k = 0; k < 32; k++) {
            float w = Ws[h0 + k];
            ull w2 = pk2(w, w);
            float4 p4 = *(const float4*)&Ps[k * 68 + ty * 4];
            float2 q2 = *(const float2*)&Qs[k * 66 + tx * 2];
            ull pp[2] = { pk2(p4.x, p4.y), pk2(p4.z, p4.w) };
            ull qd[2] = { pk2(q2.x, q2.x), pk2(q2.y, q2.y) };
            #pragma unroll
            for (int mp = 0; mp < 2; mp++) {
                #pragma unroll
                for (int n = 0; n < 2; n++) {
                    ull sum;
                    F32X2_ADD(sum, pp[mp], qd[n]);
                    float2 sv = upk2(sum);
                    sv.x = fmaxf(sv.x, 0.f);
                    sv.y = fmaxf(sv.y, 0.f);
                    ull rv = pk2(sv.x, sv.y);
                    F32X2_FMA(acc2[mp][n], rv, w2, acc2[mp][n]);
                }
            }
        }
    }
    float bb = be2[0];
    #pragma unroll
    for (int mp = 0; mp < 2; mp++) {
        float2 c0 = upk2(acc2[mp][0]);
        float2 c1 = upk2(acc2[mp][1]);
        float2 o0, o1;
        o0.x = 1.0f / (1.0f + __expf(-(c0.x + bb)));
        o0.y = 1.0f / (1.0f + __expf(-(c1.x + bb)));
        o1.x = 1.0f / (1.0f + __expf(-(c0.y + bb)));
        o1.y = 1.0f / (1.0f + __expf(-(c1.y + bb)));
        *(float2*)&g_sig[(i0 + ty * 4 + mp * 2 + 0) * NN + j0 + tx * 2] = o0;
        *(float2*)&g_sig[(i0 + ty * 4 + mp * 2 + 1) * NN + j0 + tx * 2] = o1;
    }
}

// ------------------- symmetrize -------------------
__global__ void __launch_bounds__(512)
k_sym(float* __restrict__ out) {
    __shared__ __align__(16) float T[64 * 65];
    const int r0 = (blockIdx.x / 12) * 64;
    const int c0 = (blockIdx.x % 12) * 64;
    const int tid = threadIdx.x;
    int row = tid >> 3, c8 = (tid & 7) * 8;
    float4 v0 = *(const float4*)&g_sig[(c0 + row) * NN + r0 + c8];
    float4 v1 = *(const float4*)&g_sig[(c0 + row) * NN + r0 + c8 + 4];
    T[row * 65 + c8 + 0] = v0.x; T[row * 65 + c8 + 1] = v0.y;
    T[row * 65 + c8 + 2] = v0.z; T[row * 65 + c8 + 3] = v0.w;
    T[row * 65 + c8 + 4] = v1.x; T[row * 65 + c8 + 5] = v1.y;
    T[row * 65 + c8 + 6] = v1.z; T[row * 65 + c8 + 7] = v1.w;
    __syncthreads();
    float4 a0 = *(const float4*)&g_sig[(r0 + row) * NN + c0 + c8];
    float4 a1 = *(const float4*)&g_sig[(r0 + row) * NN + c0 + c8 + 4];
    float o[8] = {a0.x, a0.y, a0.z, a0.w, a1.x, a1.y, a1.z, a1.w};
    #pragma unroll
    for (int i = 0; i < 8; i++)
        o[i] = 0.5f * (o[i] + T[(c8 + i) * 65 + row]);
    *(float4*)&out[(r0 + row) * NN + c0 + c8]     = make_float4(o[0], o[1], o[2], o[3]);
    *(float4*)&out[(r0 + row) * NN + c0 + c8 + 4] = make_float4(o[4], o[5], o[6], o[7]);
}

// ------------------- launch -------------------
extern "C" void kernel_launch(void* const* d_in, const int* in_sizes, int n_in,
                              void* d_out, int out_size) {
    const float* x        = (const float*)d_in[0];
    const float* adj      = (const float*)d_in[1];
    const float* w1       = (const float*)d_in[2];
    const float* w2       = (const float*)d_in[3];
    const float* time_emb = (const float*)d_in[4];
    const float* we1      = (const float*)d_in[5];
    const float* be1      = (const float*)d_in[6];
    const float* we2      = (const float*)d_in[7];
    const float* be2      = (const float*)d_in[8];
    const int*   t_ptr    = (const int*)d_in[9];
    float* out = (float*)d_out;

    float *S2, *hf;
    cudaGetSymbolAddress((void**)&S2, g_S2);
    cudaGetSymbolAddress((void**)&hf, g_hf);

    k_pre<<<144, 512>>>(x, w1, adj, time_emb, t_ptr, we1, be1);
    k_adj<<<288, 256>>>(adj, S2);      // S1 = (adj+I) @ (dinv*(xw0+xw1))  [24 slabs, bf16 mma]
    k_red<<<96, 256>>>(hf);            // h1f = relu(dinv * sum24 S1)
    k_hw<<<96, 512>>>(w2);             // S2 = h1f @ w2                    [2 slabs]
    k_adj<<<288, 256>>>(adj, S2);      // S1 = (adj+I) @ (dinv*(hw0+hw1))  [24 slabs, bf16 mma]
    k_red<<<96, 256>>>(hf);            // h2f = relu(dinv * sum24 S1)
    k_pq<<<96, 512>>>();               // pqf = h2f @ bpack (+c)
    k_edge<<<144, 512>>>(we2, be2);    // sig
    k_sym<<<144, 512>>>(out);          // out = (sig+sig^T)/2
}